// round 6
// baseline (speedup 1.0000x reference)
#include <cuda_runtime.h>
#include <cuda_bf16.h>
#include <cstdint>

#define EMBED 1024
#define HID   128
#define NQ    65536
#define NP    512
#define MT    128   // M tile per CTA
#define KC    32    // K chunk per mainloop iter

// Scratch (no allocations allowed): W1 top half transposed to bf16 [n][k],
// and Pb = prototypes @ W1_bottom + b1.
__device__ __align__(16) __nv_bfloat16 g_W1t[HID * EMBED];
__device__ __align__(16) float g_Pb[NP * HID];

// ---------------------------------------------------------------------------
// Kernel 1: transpose + convert W1_top (rows 0..1023 of W1[2048,128]) into
// g_W1t[n][k] bf16. 128K elements, trivial.
// ---------------------------------------------------------------------------
__global__ void w1t_kernel(const float* __restrict__ W1) {
    int t = blockIdx.x * blockDim.x + threadIdx.x;  // 0 .. HID*EMBED-1
    int n = t >> 10;        // 0..127
    int k = t & 1023;       // 0..1023
    g_W1t[(size_t)n * EMBED + k] = __float2bfloat16(W1[(size_t)k * HID + n]);
}

// ---------------------------------------------------------------------------
// Kernel 2: Pb[p][j] = sum_k proto[p][k] * W1[1024+k][j] + b1[j]
// 4 prototypes per block, split-K x2 across 256 threads, fp32.
// ---------------------------------------------------------------------------
__global__ void proto_kernel(const float* __restrict__ proto,
                             const float* __restrict__ W1,
                             const float* __restrict__ b1) {
    __shared__ float sp[4 * EMBED];
    __shared__ float spart[4][HID];
    int t  = threadIdx.x;
    int j  = t & (HID - 1);
    int kh = t >> 7;                 // 0 or 1 (K half)
    int p0 = blockIdx.x * 4;

    // load 4 contiguous prototype rows (4096 floats) into smem
    for (int i = t * 4; i < 4 * EMBED; i += 256 * 4)
        *(float4*)(sp + i) = *(const float4*)(proto + (size_t)p0 * EMBED + i);
    __syncthreads();

    float a0 = 0.f, a1 = 0.f, a2 = 0.f, a3 = 0.f;
    int kbeg = kh * (EMBED / 2);
#pragma unroll 4
    for (int k = kbeg; k < kbeg + EMBED / 2; k++) {
        float w = W1[(size_t)(EMBED + k) * HID + j];   // coalesced across j
        a0 += sp[0 * EMBED + k] * w;
        a1 += sp[1 * EMBED + k] * w;
        a2 += sp[2 * EMBED + k] * w;
        a3 += sp[3 * EMBED + k] * w;
    }
    if (kh == 1) {
        spart[0][j] = a0; spart[1][j] = a1; spart[2][j] = a2; spart[3][j] = a3;
    }
    __syncthreads();
    if (kh == 0) {
        float bb = b1[j];
        g_Pb[(size_t)(p0 + 0) * HID + j] = a0 + spart[0][j] + bb;
        g_Pb[(size_t)(p0 + 1) * HID + j] = a1 + spart[1][j] + bb;
        g_Pb[(size_t)(p0 + 2) * HID + j] = a2 + spart[2][j] + bb;
        g_Pb[(size_t)(p0 + 3) * HID + j] = a3 + spart[3][j] + bb;
    }
}

// ---------------------------------------------------------------------------
// Kernel 3: fused argmin + GEMM (Q@W1_top, bf16 mma.sync) + epilogue
// (+Pb[idx], relu, dot W2, sigmoid).
// CTA: 128 queries x 128 hidden, 256 threads (8 warps: 4 along M x 2 along N).
// ---------------------------------------------------------------------------
__global__ __launch_bounds__(256)
void fused_kernel(const float* __restrict__ Q,
                  const float* __restrict__ dist,
                  const float* __restrict__ W2,
                  const float* __restrict__ b2,
                  float* __restrict__ out) {
    __shared__ __align__(16) __nv_bfloat16 As[MT][40];   // pad 40 -> conflict-free frag reads
    __shared__ __align__(16) __nv_bfloat16 Bs[HID][40];  // [n][k] layout
    __shared__ int   s_idx[MT];
    __shared__ float s_w2[HID];
    __shared__ float s_rowsum[MT];

    const int t    = threadIdx.x;
    const int warp = t >> 5, lane = t & 31;
    const int m0   = blockIdx.x * MT;

    // ---- argmin prologue: warp w handles queries w, w+8, ..., w+120 ----
    for (int i = 0; i < 16; i++) {
        int qi = warp + i * 8;
        const float* row = dist + (size_t)(m0 + qi) * NP;
        float best = 3.4e38f; int bi = 0;
#pragma unroll
        for (int it = 0; it < 4; it++) {
            int j = it * 128 + lane * 4;
            float4 v = *(const float4*)(row + j);
            if (v.x < best) { best = v.x; bi = j; }
            if (v.y < best) { best = v.y; bi = j + 1; }
            if (v.z < best) { best = v.z; bi = j + 2; }
            if (v.w < best) { best = v.w; bi = j + 3; }
        }
#pragma unroll
        for (int off = 16; off; off >>= 1) {
            float ov = __shfl_down_sync(0xffffffffu, best, off);
            int   oi = __shfl_down_sync(0xffffffffu, bi,   off);
            if (ov < best || (ov == best && oi < bi)) { best = ov; bi = oi; }
        }
        if (lane == 0) s_idx[qi] = bi;
    }
    if (t < HID) s_w2[t] = W2[t];
    if (t < MT)  s_rowsum[t] = 0.f;

    float acc[2][8][4];
#pragma unroll
    for (int mi = 0; mi < 2; mi++)
#pragma unroll
        for (int ni = 0; ni < 8; ni++)
#pragma unroll
            for (int r = 0; r < 4; r++) acc[mi][ni][r] = 0.f;

    const int warpM = warp >> 1;   // 0..3 : rows warpM*32
    const int warpN = warp & 1;    // 0..1 : cols warpN*64
    const int g  = lane >> 2;      // 0..7
    const int qd = lane & 3;       // 0..3

    // ---- mainloop over K ----
    for (int k0 = 0; k0 < EMBED; k0 += KC) {
        // load A chunk: 128 x 32 fp32 -> bf16, coalesced float4
        {
            int ar = t >> 3;            // 0..31
            int ac = (t & 7) << 2;      // 0,4,...,28
#pragma unroll
            for (int p = 0; p < 4; p++) {
                int row = ar + p * 32;
                float4 v = *(const float4*)(Q + (size_t)(m0 + row) * EMBED + k0 + ac);
                __nv_bfloat162* dst = (__nv_bfloat162*)&As[row][ac];
                dst[0] = __floats2bfloat162_rn(v.x, v.y);
                dst[1] = __floats2bfloat162_rn(v.z, v.w);
            }
        }
        // load B chunk from pre-transposed g_W1t[n][k]: 128 x 32 bf16
        {
            int n  = t >> 1;            // 0..127
            int kc = (t & 1) << 4;      // 0 or 16
            const __nv_bfloat16* src = g_W1t + (size_t)n * EMBED + k0 + kc;
            uint4 v0 = *(const uint4*)(src);
            uint4 v1 = *(const uint4*)(src + 8);
            *(uint4*)&Bs[n][kc]     = v0;
            *(uint4*)&Bs[n][kc + 8] = v1;
        }
        __syncthreads();

#pragma unroll
        for (int ks = 0; ks < 2; ks++) {
            const int ko = ks * 16;
            uint32_t a[2][4];
#pragma unroll
            for (int mi = 0; mi < 2; mi++) {
                int row = warpM * 32 + mi * 16 + g;
                a[mi][0] = *(const uint32_t*)&As[row    ][ko + qd * 2];
                a[mi][1] = *(const uint32_t*)&As[row + 8][ko + qd * 2];
                a[mi][2] = *(const uint32_t*)&As[row    ][ko + qd * 2 + 8];
                a[mi][3] = *(const uint32_t*)&As[row + 8][ko + qd * 2 + 8];
            }
            uint32_t b[8][2];
#pragma unroll
            for (int ni = 0; ni < 8; ni++) {
                int n = warpN * 64 + ni * 8 + g;
                b[ni][0] = *(const uint32_t*)&Bs[n][ko + qd * 2];
                b[ni][1] = *(const uint32_t*)&Bs[n][ko + qd * 2 + 8];
            }
#pragma unroll
            for (int mi = 0; mi < 2; mi++)
#pragma unroll
                for (int ni = 0; ni < 8; ni++)
                    asm volatile(
                        "mma.sync.aligned.m16n8k16.row.col.f32.bf16.bf16.f32 "
                        "{%0,%1,%2,%3}, {%4,%5,%6,%7}, {%8,%9}, {%0,%1,%2,%3};\n"
                        : "+f"(acc[mi][ni][0]), "+f"(acc[mi][ni][1]),
                          "+f"(acc[mi][ni][2]), "+f"(acc[mi][ni][3])
                        : "r"(a[mi][0]), "r"(a[mi][1]), "r"(a[mi][2]), "r"(a[mi][3]),
                          "r"(b[ni][0]), "r"(b[ni][1]));
        }
        __syncthreads();
    }

    // ---- epilogue: +Pb[idx], relu, * W2, row-reduce, sigmoid ----
    // fragment mapping (m16n8k16): c{0,1}: row g,  cols qd*2, qd*2+1
    //                              c{2,3}: row g+8, same cols
#pragma unroll
    for (int mi = 0; mi < 2; mi++) {
#pragma unroll
        for (int rr = 0; rr < 2; rr++) {
            int rloc = warpM * 32 + mi * 16 + rr * 8 + g;
            const float* Pr = g_Pb + (size_t)s_idx[rloc] * HID;
            float s = 0.f;
#pragma unroll
            for (int ni = 0; ni < 8; ni++) {
                int c = warpN * 64 + ni * 8 + qd * 2;
                float v0 = acc[mi][ni][rr * 2 + 0] + Pr[c];
                float v1 = acc[mi][ni][rr * 2 + 1] + Pr[c + 1];
                s += fmaxf(v0, 0.f) * s_w2[c] + fmaxf(v1, 0.f) * s_w2[c + 1];
            }
            atomicAdd(&s_rowsum[rloc], s);
        }
    }
    __syncthreads();
    if (t < MT) {
        float z = s_rowsum[t] + b2[0];
        out[m0 + t] = 1.f / (1.f + __expf(-z));
    }
}

// ---------------------------------------------------------------------------
extern "C" void kernel_launch(void* const* d_in, const int* in_sizes, int n_in,
                              void* d_out, int out_size) {
    const float* Q     = (const float*)d_in[0];   // [65536,1024]
    const float* proto = (const float*)d_in[1];   // [512,1024]
    const float* dist  = (const float*)d_in[2];   // [65536,512]
    const float* W1    = (const float*)d_in[3];   // [2048,128]
    const float* b1    = (const float*)d_in[4];   // [128]
    const float* W2    = (const float*)d_in[5];   // [128,1]
    const float* b2    = (const float*)d_in[6];   // [1]
    float* out = (float*)d_out;                   // [65536]

    w1t_kernel<<<(HID * EMBED) / 256, 256>>>(W1);
    proto_kernel<<<NP / 4, 256>>>(proto, W1, b1);
    fused_kernel<<<NQ / MT, 256>>>(Q, dist, W2, b2, out);
}